// round 1
// baseline (speedup 1.0000x reference)
#include <cuda_runtime.h>
#include <cstdint>

#define N_FEAT 512
#define N_HID  16
#define N_CLS  40
#define MAX_NODES 100000

// Scratch (allocation-free: __device__ globals)
__device__ float g_support1[MAX_NODES * N_HID];  // X @ W1
__device__ float g_agg1[MAX_NODES * N_HID];      // segment_sum conv1
__device__ float g_h[MAX_NODES * N_HID];         // relu(agg1 + b1)
__device__ float g_agg2[MAX_NODES * N_HID];      // segment_sum of h (16-dim!)

// ---------------------------------------------------------------------------
// packed f32x2 helpers (sm_100+)
// ---------------------------------------------------------------------------
#define FMA_F32X2(d, a, b, c) \
    asm("fma.rn.f32x2 %0, %1, %2, %3;" : "=l"(d) : "l"(a), "l"(b), "l"(c))

// ---------------------------------------------------------------------------
// Kernel 0: zero both aggregation buffers
// ---------------------------------------------------------------------------
__global__ void zero_kernel(int n_float4) {
    int i = blockIdx.x * blockDim.x + threadIdx.x;
    if (i >= n_float4) return;
    float4 z = make_float4(0.f, 0.f, 0.f, 0.f);
    reinterpret_cast<float4*>(g_agg1)[i] = z;
    reinterpret_cast<float4*>(g_agg2)[i] = z;
}

// ---------------------------------------------------------------------------
// Kernel 1: support1 = X @ W1   [nNodes,512] @ [512,16]
// One thread per row. W1 staged in shared. Packed f32x2 FMA (2 MACs/instr).
// ---------------------------------------------------------------------------
__global__ __launch_bounds__(256) void gemm1_kernel(
    const float* __restrict__ X, const float* __restrict__ W1, int nNodes)
{
    __shared__ __align__(16) float sW[N_FEAT * N_HID];  // 32 KB
    for (int i = threadIdx.x; i < N_FEAT * N_HID; i += blockDim.x)
        sW[i] = W1[i];
    __syncthreads();

    int row = blockIdx.x * blockDim.x + threadIdx.x;
    if (row >= nNodes) return;

    const float4* xr = reinterpret_cast<const float4*>(X + (size_t)row * N_FEAT);

    unsigned long long acc[8];  // acc[p] = packed (col 2p, col 2p+1)
    #pragma unroll
    for (int p = 0; p < 8; p++) acc[p] = 0ULL;  // (0.f,0.f) bit pattern

    #pragma unroll 2
    for (int k4 = 0; k4 < N_FEAT / 4; k4++) {
        float4 xv = xr[k4];
        #pragma unroll
        for (int t = 0; t < 4; t++) {
            float xs = (t == 0) ? xv.x : (t == 1) ? xv.y : (t == 2) ? xv.z : xv.w;
            unsigned long long xx;
            asm("mov.b64 %0, {%1, %1};" : "=l"(xx) : "f"(xs));
            const float* wrow = sW + (k4 * 4 + t) * N_HID;
            #pragma unroll
            for (int q = 0; q < 2; q++) {
                // ld.shared.v4 -> two packed f32x2 (cols 8q..8q+3 in .x/.y... actually 4 cols per ull2)
                ulonglong2 w0 = *reinterpret_cast<const ulonglong2*>(wrow + q * 8);
                FMA_F32X2(acc[q * 4 + 0], xx, w0.x, acc[q * 4 + 0]);
                FMA_F32X2(acc[q * 4 + 1], xx, w0.y, acc[q * 4 + 1]);
                ulonglong2 w1 = *reinterpret_cast<const ulonglong2*>(wrow + q * 8 + 4);
                FMA_F32X2(acc[q * 4 + 2], xx, w1.x, acc[q * 4 + 2]);
                FMA_F32X2(acc[q * 4 + 3], xx, w1.y, acc[q * 4 + 3]);
            }
        }
    }

    float* o = g_support1 + (size_t)row * N_HID;
    #pragma unroll
    for (int q = 0; q < 4; q++) {
        ulonglong2 st;
        st.x = acc[q * 2 + 0];
        st.y = acc[q * 2 + 1];
        *reinterpret_cast<ulonglong2*>(o + q * 4) = st;
    }
}

// ---------------------------------------------------------------------------
// Kernel 2: edge aggregation (16 features).
// One thread per (edge, 4-float chunk). Vector atomic red.global.add.v4.f32.
// ---------------------------------------------------------------------------
__global__ __launch_bounds__(256) void aggregate_kernel(
    const int* __restrict__ src, const int* __restrict__ dst,
    const float* __restrict__ ew, const float* __restrict__ feat,
    float* __restrict__ out, int nEdges)
{
    int gid = blockIdx.x * blockDim.x + threadIdx.x;
    int e = gid >> 2;
    if (e >= nEdges) return;
    int c = (gid & 3) << 2;

    int s = __ldg(src + e);
    int d = __ldg(dst + e);
    float w = __ldg(ew + e);

    float4 v = *reinterpret_cast<const float4*>(feat + s * N_HID + c);
    float* o = out + d * N_HID + c;
    asm volatile("red.global.add.v4.f32 [%0], {%1, %2, %3, %4};"
                 :: "l"(o), "f"(v.x * w), "f"(v.y * w), "f"(v.z * w), "f"(v.w * w)
                 : "memory");
}

// ---------------------------------------------------------------------------
// Kernel 3: h = relu(agg1 + b1)
// ---------------------------------------------------------------------------
__global__ __launch_bounds__(256) void relu_bias_kernel(
    const float* __restrict__ b1, int n_float4)
{
    int i = blockIdx.x * blockDim.x + threadIdx.x;
    if (i >= n_float4) return;
    int j = (i & 3) << 2;  // column group within the 16-wide row
    float4 v = reinterpret_cast<const float4*>(g_agg1)[i];
    float4 b = *reinterpret_cast<const float4*>(b1 + j);
    v.x = fmaxf(v.x + b.x, 0.f);
    v.y = fmaxf(v.y + b.y, 0.f);
    v.z = fmaxf(v.z + b.z, 0.f);
    v.w = fmaxf(v.w + b.w, 0.f);
    reinterpret_cast<float4*>(g_h)[i] = v;
}

// ---------------------------------------------------------------------------
// Kernel 4: out = log_softmax(agg2 @ W2 + b2)
// (aggregation was done in 16-dim; project to 40 classes here — linearity)
// ---------------------------------------------------------------------------
__global__ __launch_bounds__(128) void head_kernel(
    const float* __restrict__ W2, const float* __restrict__ b2,
    float* __restrict__ out, int nNodes)
{
    __shared__ float sW[N_HID * N_CLS];  // 2.56 KB
    __shared__ float sb[N_CLS];
    for (int i = threadIdx.x; i < N_HID * N_CLS; i += blockDim.x) sW[i] = W2[i];
    for (int i = threadIdx.x; i < N_CLS; i += blockDim.x) sb[i] = b2[i];
    __syncthreads();

    int node = blockIdx.x * blockDim.x + threadIdx.x;
    if (node >= nNodes) return;

    float v[N_HID];
    const float4* vp = reinterpret_cast<const float4*>(g_agg2 + (size_t)node * N_HID);
    #pragma unroll
    for (int q = 0; q < 4; q++) {
        float4 t = vp[q];
        v[q * 4 + 0] = t.x; v[q * 4 + 1] = t.y; v[q * 4 + 2] = t.z; v[q * 4 + 3] = t.w;
    }

    float y[N_CLS];
    #pragma unroll
    for (int cc = 0; cc < N_CLS; cc++) y[cc] = sb[cc];

    for (int k = 0; k < N_HID; k++) {
        float vk = v[k];
        const float* wr = sW + k * N_CLS;
        #pragma unroll
        for (int cc = 0; cc < N_CLS; cc++)
            y[cc] = fmaf(vk, wr[cc], y[cc]);
    }

    // log_softmax
    float mx = y[0];
    #pragma unroll
    for (int cc = 1; cc < N_CLS; cc++) mx = fmaxf(mx, y[cc]);
    float sum = 0.f;
    #pragma unroll
    for (int cc = 0; cc < N_CLS; cc++) sum += __expf(y[cc] - mx);
    float lse = mx + __logf(sum);

    float* o = out + (size_t)node * N_CLS;
    #pragma unroll
    for (int q = 0; q < N_CLS / 4; q++) {
        float4 st = make_float4(y[q * 4 + 0] - lse, y[q * 4 + 1] - lse,
                                y[q * 4 + 2] - lse, y[q * 4 + 3] - lse);
        *reinterpret_cast<float4*>(o + q * 4) = st;
    }
}

// ---------------------------------------------------------------------------
// Launcher
// ---------------------------------------------------------------------------
extern "C" void kernel_launch(void* const* d_in, const int* in_sizes, int n_in,
                              void* d_out, int out_size)
{
    const float* x        = (const float*)d_in[0];
    const int*   edge_src = (const int*)  d_in[1];
    const int*   edge_dst = (const int*)  d_in[2];
    const float* edge_w   = (const float*)d_in[3];
    const float* W1       = (const float*)d_in[4];
    const float* b1       = (const float*)d_in[5];
    const float* W2       = (const float*)d_in[6];
    const float* b2       = (const float*)d_in[7];
    float* out = (float*)d_out;

    int nNodes = in_sizes[0] / N_FEAT;
    int nEdges = in_sizes[1];

    float* d_support1; cudaGetSymbolAddress((void**)&d_support1, g_support1);
    float* d_agg1;     cudaGetSymbolAddress((void**)&d_agg1, g_agg1);
    float* d_h;        cudaGetSymbolAddress((void**)&d_h, g_h);
    float* d_agg2;     cudaGetSymbolAddress((void**)&d_agg2, g_agg2);

    int n_f4 = nNodes * N_HID / 4;

    zero_kernel<<<(n_f4 + 255) / 256, 256>>>(n_f4);

    gemm1_kernel<<<(nNodes + 255) / 256, 256>>>(x, W1, nNodes);

    int aggThreads = nEdges * 4;
    aggregate_kernel<<<(aggThreads + 255) / 256, 256>>>(
        edge_src, edge_dst, edge_w, d_support1, d_agg1, nEdges);

    relu_bias_kernel<<<(n_f4 + 255) / 256, 256>>>(b1, n_f4);

    aggregate_kernel<<<(aggThreads + 255) / 256, 256>>>(
        edge_src, edge_dst, edge_w, d_h, d_agg2, nEdges);

    head_kernel<<<(nNodes + 127) / 128, 128>>>(W2, b2, out, nNodes);
}